// round 15
// baseline (speedup 1.0000x reference)
#include <cuda_runtime.h>
#include <cstdint>

// Problem constants (fixed shapes for this problem)
#define BB     4
#define NA     49104
#define NC     80
#define KPRE   1000
#define MAXBOX 100
#define NPAIR  (BB*NC)
#define CAND_N (NC*KPRE)

// ---------------- scratch (static device globals; no allocations) ----------
__device__ uint32_t g_keys[(size_t)BB * NC * NA];   // ~63 MB: prob bits, transposed [B,C,N]
__device__ float4   g_boxes[BB * NA];               // decoded clipped boxes xyxy
__device__ int      g_selidx[NPAIR * KPRE];         // top-1000 anchor ids per (b,c), sorted
__device__ uint32_t g_selkey[NPAIR * KPRE];         // their prob bits (0 = invalid)
__device__ uint32_t g_cand[NPAIR * KPRE];           // post-NMS candidate keys

// ---------------- stage 1: box decode + clip -------------------------------
__global__ void decode_kernel(const float4* __restrict__ anchors,
                              const float4* __restrict__ reg) {
    int t = blockIdx.x * blockDim.x + threadIdx.x;
    if (t >= BB * NA) return;
    float4 a = anchors[t];   // (y1, x1, y2, x2)
    float4 r = reg[t];       // (dy, dx, dh, dw)
    float yca = (a.x + a.z) * 0.5f;
    float xca = (a.y + a.w) * 0.5f;
    float ha = a.z - a.x;
    float wa = a.w - a.y;
    float w = expf(r.w) * wa;
    float h = expf(r.z) * ha;
    float yc = r.x * ha + yca;
    float xc = r.y * wa + xca;
    float4 o;
    o.x = fmaxf(xc - w * 0.5f, 0.0f);
    o.y = fmaxf(yc - h * 0.5f, 0.0f);
    o.z = fminf(xc + w * 0.5f, 511.0f);
    o.w = fminf(yc + h * 0.5f, 511.0f);
    g_boxes[t] = o;
}

// ---------------- stage 2: sigmoid + threshold + transpose to [B,C,N] ------
__global__ void sigmoid_transpose_kernel(const float* __restrict__ cls) {
    __shared__ uint32_t tile[32][33];
    int b  = blockIdx.z;
    int n0 = blockIdx.x << 5;
    int c0 = blockIdx.y << 5;
    int c = c0 + threadIdx.x;
    int n = n0 + threadIdx.y;
    uint32_t v = 0u;
    if (n < NA && c < NC) {
        float x = cls[((size_t)b * NA + n) * NC + c];
        float p;
        if (x >= 0.0f) { p = 1.0f / (1.0f + expf(-x)); }
        else           { float e = expf(x); p = e / (1.0f + e); }
        v = (p > 0.01f) ? __float_as_uint(p) : 0u;   // positive float bits are order-preserving
    }
    tile[threadIdx.y][threadIdx.x] = v;
    __syncthreads();
    int cc = c0 + threadIdx.y;
    int nn = n0 + threadIdx.x;
    if (nn < NA && cc < NC)
        g_keys[((size_t)b * NC + cc) * NA + nn] = tile[threadIdx.x][threadIdx.y];
}

// ---------------- generic exact top-K sorted (key desc, idx asc) -----------
// Radix-select (4 x 8-bit passes) finds exact pivot + count of equals to take;
// collection + bitonic sort produce the K best in sorted order.
template <int K, int PADK, int T>
__device__ void topk_sorted(const uint32_t* __restrict__ keys, int n,
                            uint32_t* sh_key, int* sh_idx, int* sh_eq,
                            uint32_t* hist) {
    int tid = threadIdx.x;
    __shared__ uint32_t s_prefix;
    __shared__ int s_kth, s_chi, s_ceq;
    if (tid == 0) { s_prefix = 0u; s_kth = K; }

    for (int pass = 0; pass < 4; pass++) {
        int shift = 24 - 8 * pass;
        for (int d = tid; d < 256; d += T) hist[d] = 0u;
        __syncthreads();
        uint32_t prefix = s_prefix;
        uint32_t maskhi = pass ? (0xFFFFFFFFu << (shift + 8)) : 0u;
        for (int i = tid; i < n; i += T) {
            uint32_t kv = keys[i];
            if ((kv & maskhi) == prefix)
                atomicAdd(&hist[(kv >> shift) & 255u], 1u);
        }
        __syncthreads();
        if (tid == 0) {
            int kth = s_kth;
            int c = 0;
            for (int d = 255; d >= 0; d--) {
                c += (int)hist[d];
                if (c >= kth) {
                    s_prefix = prefix | ((uint32_t)d << shift);
                    s_kth = kth - (c - (int)hist[d]);
                    break;
                }
            }
        }
        __syncthreads();
    }

    uint32_t pivot = s_prefix;
    int rem = s_kth;   // how many ==pivot to take
    if (tid == 0) { s_chi = 0; s_ceq = 0; }
    __syncthreads();

    for (int i = tid; i < n; i += T) {
        uint32_t kv = keys[i];
        if (kv > pivot) {
            int p = atomicAdd(&s_chi, 1);
            sh_key[p] = kv; sh_idx[p] = i;
        } else if (kv == pivot) {
            int p = atomicAdd(&s_ceq, 1);
            if (p < rem) sh_eq[p] = i;
        }
    }
    __syncthreads();
    int chi = s_chi;   // == K - rem by construction
    for (int j = tid; j < rem; j += T) { sh_key[chi + j] = pivot; sh_idx[chi + j] = sh_eq[j]; }
    for (int j = K + tid; j < PADK; j += T) { sh_key[j] = 0u; sh_idx[j] = 0x7FFFFFFF; }
    __syncthreads();

    // bitonic sort: best-first (key desc, idx asc)
    for (int size = 2; size <= PADK; size <<= 1) {
        for (int stride = size >> 1; stride > 0; stride >>= 1) {
            for (int i = tid; i < PADK; i += T) {
                int j = i ^ stride;
                if (j > i) {
                    uint32_t ki = sh_key[i], kj = sh_key[j];
                    int ii = sh_idx[i], ij = sh_idx[j];
                    bool jBetter = (kj > ki) || (kj == ki && ij < ii);
                    bool dirDesc = ((i & size) == 0);
                    if (dirDesc == jBetter) {
                        sh_key[i] = kj; sh_key[j] = ki;
                        sh_idx[i] = ij; sh_idx[j] = ii;
                    }
                }
            }
            __syncthreads();
        }
    }
}

// ---------------- stage 3: per-(b,c) top-1000 sorted ------------------------
__global__ void __launch_bounds__(512) select_kernel() {
    __shared__ uint32_t hist[256];
    __shared__ uint32_t sh_key[1024];
    __shared__ int sh_idx[1024];
    __shared__ int sh_eq[KPRE];
    int pair = blockIdx.x;
    topk_sorted<KPRE, 1024, 512>(g_keys + (size_t)pair * NA, NA,
                                 sh_key, sh_idx, sh_eq, hist);
    for (int k = threadIdx.x; k < KPRE; k += 512) {
        g_selidx[pair * KPRE + k] = sh_idx[k];
        g_selkey[pair * KPRE + k] = sh_key[k];
    }
}

// ---------------- stage 4: greedy NMS per (b,c) -----------------------------
__global__ void __launch_bounds__(256) nms_kernel() {
    int pair = blockIdx.x;
    int b = pair / NC;
    __shared__ float4 bx[KPRE];
    __shared__ float  area[KPRE];
    __shared__ int    keep[KPRE];
    int tid = threadIdx.x;

    for (int k = tid; k < KPRE; k += 256) {
        int idx = g_selidx[pair * KPRE + k];
        float4 v = g_boxes[b * NA + idx];
        bx[k] = v;
        area[k] = (v.z - v.x) * (v.w - v.y);
        keep[k] = (g_selkey[pair * KPRE + k] != 0u) ? 1 : 0;
    }
    __syncthreads();

    for (int i = 0; i < KPRE; i++) {
        if (keep[i]) {  // uniform read of shared -> no divergence across block
            float4 bi = bx[i];
            float ai = area[i];
            for (int j = i + 1 + tid; j < KPRE; j += 256) {
                if (keep[j]) {
                    float xx1 = fmaxf(bi.x, bx[j].x);
                    float yy1 = fmaxf(bi.y, bx[j].y);
                    float xx2 = fminf(bi.z, bx[j].z);
                    float yy2 = fminf(bi.w, bx[j].w);
                    float iw = fmaxf(xx2 - xx1, 0.0f);
                    float ih = fmaxf(yy2 - yy1, 0.0f);
                    float inter = iw * ih;
                    float u = ai + area[j] - inter;
                    if (inter / u > 0.5f) keep[j] = 0;   // NaN compares false, matches JAX
                }
            }
        }
        __syncthreads();
    }

    for (int k = tid; k < KPRE; k += 256)
        g_cand[pair * KPRE + k] = keep[k] ? g_selkey[pair * KPRE + k] : 0u;
}

// ---------------- stage 5: per-image top-100 + outputs ----------------------
__global__ void __launch_bounds__(512) final_kernel(const float* __restrict__ scale,
                                                    float* __restrict__ out) {
    __shared__ uint32_t hist[256];
    __shared__ uint32_t sh_key[128];
    __shared__ int sh_idx[128];
    __shared__ int sh_eq[MAXBOX];
    int b = blockIdx.x;
    topk_sorted<MAXBOX, 128, 512>(g_cand + (size_t)b * CAND_N, CAND_N,
                                  sh_key, sh_idx, sh_eq, hist);
    int tid = threadIdx.x;
    if (tid < MAXBOX) {
        uint32_t key = sh_key[tid];
        int f = sh_idx[tid];
        float prob = __uint_as_float(key);
        bool val = prob > 0.01f;
        int c = f / KPRE;
        int k = f - c * KPRE;
        int anchor = g_selidx[(b * NC + c) * KPRE + k];
        float4 bxv = g_boxes[b * NA + anchor];
        float s = scale[b];
        int o = (b * MAXBOX + tid) * 4;
        out[o + 0] = val ? bxv.x / s : 0.0f;
        out[o + 1] = val ? bxv.y / s : 0.0f;
        out[o + 2] = val ? bxv.z / s : 0.0f;
        out[o + 3] = val ? bxv.w / s : 0.0f;
        out[BB * MAXBOX * 4 + b * MAXBOX + tid]               = val ? (float)c : -1.0f;
        out[BB * MAXBOX * 4 + BB * MAXBOX + b * MAXBOX + tid] = val ? prob : 0.0f;
    }
}

// ---------------- launcher ---------------------------------------------------
extern "C" void kernel_launch(void* const* d_in, const int* in_sizes, int n_in,
                              void* d_out, int out_size) {
    // inputs (metadata order): image, anchors, regression, classification, scale
    const float4* anchors    = (const float4*)d_in[1];
    const float4* regression = (const float4*)d_in[2];
    const float*  cls        = (const float*)d_in[3];
    const float*  scale      = (const float*)d_in[4];

    decode_kernel<<<(BB * NA + 255) / 256, 256>>>(anchors, regression);

    dim3 tg((NA + 31) / 32, (NC + 31) / 32, BB);
    sigmoid_transpose_kernel<<<tg, dim3(32, 32)>>>(cls);

    select_kernel<<<NPAIR, 512>>>();
    nms_kernel<<<NPAIR, 256>>>();
    final_kernel<<<BB, 512>>>(scale, (float*)d_out);
}

// round 16
// speedup vs baseline: 1.0497x; 1.0497x over previous
#include <cuda_runtime.h>
#include <cstdint>

// Problem constants (fixed shapes for this problem)
#define BB     4
#define NA     49104
#define NC     80
#define KPRE   1000
#define MAXBOX 100
#define NPAIR  (BB*NC)
#define CAND_N (NC*KPRE)

// ---------------- scratch (static device globals; no allocations) ----------
__device__ uint32_t g_keys[(size_t)BB * NC * NA];   // ~63 MB: prob bits, transposed [B,C,N]
__device__ float4   g_boxes[BB * NA];               // decoded clipped boxes xyxy
__device__ int      g_selidx[NPAIR * KPRE];         // top-1000 anchor ids per (b,c), sorted
__device__ uint32_t g_selkey[NPAIR * KPRE];         // their prob bits (0 = invalid)
__device__ uint32_t g_cand[NPAIR * KPRE];           // post-NMS candidate keys

// ---------------- stage 1: box decode + clip -------------------------------
__global__ void decode_kernel(const float4* __restrict__ anchors,
                              const float4* __restrict__ reg) {
    int t = blockIdx.x * blockDim.x + threadIdx.x;
    if (t >= BB * NA) return;
    float4 a = anchors[t];   // (y1, x1, y2, x2)
    float4 r = reg[t];       // (dy, dx, dh, dw)
    float yca = (a.x + a.z) * 0.5f;
    float xca = (a.y + a.w) * 0.5f;
    float ha = a.z - a.x;
    float wa = a.w - a.y;
    float w = expf(r.w) * wa;
    float h = expf(r.z) * ha;
    float yc = r.x * ha + yca;
    float xc = r.y * wa + xca;
    float4 o;
    o.x = fmaxf(xc - w * 0.5f, 0.0f);
    o.y = fmaxf(yc - h * 0.5f, 0.0f);
    o.z = fminf(xc + w * 0.5f, 511.0f);
    o.w = fminf(yc + h * 0.5f, 511.0f);
    g_boxes[t] = o;
}

// ---------------- stage 2: sigmoid + threshold + transpose to [B,C,N] ------
__global__ void sigmoid_transpose_kernel(const float* __restrict__ cls) {
    __shared__ uint32_t tile[32][33];
    int b  = blockIdx.z;
    int n0 = blockIdx.x << 5;
    int c0 = blockIdx.y << 5;
    int c = c0 + threadIdx.x;
    int n = n0 + threadIdx.y;
    uint32_t v = 0u;
    if (n < NA && c < NC) {
        float x = cls[((size_t)b * NA + n) * NC + c];
        float p;
        if (x >= 0.0f) { p = 1.0f / (1.0f + expf(-x)); }
        else           { float e = expf(x); p = e / (1.0f + e); }
        v = (p > 0.01f) ? __float_as_uint(p) : 0u;   // positive float bits are order-preserving
    }
    tile[threadIdx.y][threadIdx.x] = v;
    __syncthreads();
    int cc = c0 + threadIdx.y;
    int nn = n0 + threadIdx.x;
    if (nn < NA && cc < NC)
        g_keys[((size_t)b * NC + cc) * NA + nn] = tile[threadIdx.x][threadIdx.y];
}

// ---------------- generic exact top-K sorted (key desc, idx asc) -----------
// Radix-select (4 x 8-bit passes) finds exact pivot + count of equals to take;
// collection + bitonic sort produce the K best in sorted order.
template <int K, int PADK, int T>
__device__ void topk_sorted(const uint32_t* __restrict__ keys, int n,
                            uint32_t* sh_key, int* sh_idx, int* sh_eq,
                            uint32_t* hist) {
    int tid = threadIdx.x;
    __shared__ uint32_t s_prefix;
    __shared__ int s_kth, s_chi, s_ceq;
    if (tid == 0) { s_prefix = 0u; s_kth = K; }

    for (int pass = 0; pass < 4; pass++) {
        int shift = 24 - 8 * pass;
        for (int d = tid; d < 256; d += T) hist[d] = 0u;
        __syncthreads();
        uint32_t prefix = s_prefix;
        uint32_t maskhi = pass ? (0xFFFFFFFFu << (shift + 8)) : 0u;
        for (int i = tid; i < n; i += T) {
            uint32_t kv = keys[i];
            if ((kv & maskhi) == prefix)
                atomicAdd(&hist[(kv >> shift) & 255u], 1u);
        }
        __syncthreads();
        if (tid == 0) {
            int kth = s_kth;
            int c = 0;
            for (int d = 255; d >= 0; d--) {
                c += (int)hist[d];
                if (c >= kth) {
                    s_prefix = prefix | ((uint32_t)d << shift);
                    s_kth = kth - (c - (int)hist[d]);
                    break;
                }
            }
        }
        __syncthreads();
    }

    uint32_t pivot = s_prefix;
    int rem = s_kth;   // how many ==pivot to take
    if (tid == 0) { s_chi = 0; s_ceq = 0; }
    __syncthreads();

    for (int i = tid; i < n; i += T) {
        uint32_t kv = keys[i];
        if (kv > pivot) {
            int p = atomicAdd(&s_chi, 1);
            sh_key[p] = kv; sh_idx[p] = i;
        } else if (kv == pivot) {
            int p = atomicAdd(&s_ceq, 1);
            if (p < rem) sh_eq[p] = i;
        }
    }
    __syncthreads();
    int chi = s_chi;   // == K - rem by construction
    for (int j = tid; j < rem; j += T) { sh_key[chi + j] = pivot; sh_idx[chi + j] = sh_eq[j]; }
    for (int j = K + tid; j < PADK; j += T) { sh_key[j] = 0u; sh_idx[j] = 0x7FFFFFFF; }
    __syncthreads();

    // bitonic sort: best-first (key desc, idx asc)
    for (int size = 2; size <= PADK; size <<= 1) {
        for (int stride = size >> 1; stride > 0; stride >>= 1) {
            for (int i = tid; i < PADK; i += T) {
                int j = i ^ stride;
                if (j > i) {
                    uint32_t ki = sh_key[i], kj = sh_key[j];
                    int ii = sh_idx[i], ij = sh_idx[j];
                    bool jBetter = (kj > ki) || (kj == ki && ij < ii);
                    bool dirDesc = ((i & size) == 0);
                    if (dirDesc == jBetter) {
                        sh_key[i] = kj; sh_key[j] = ki;
                        sh_idx[i] = ij; sh_idx[j] = ii;
                    }
                }
            }
            __syncthreads();
        }
    }
}

// ---------------- stage 3: per-(b,c) top-1000 sorted ------------------------
__global__ void __launch_bounds__(512) select_kernel() {
    __shared__ uint32_t hist[256];
    __shared__ uint32_t sh_key[1024];
    __shared__ int sh_idx[1024];
    __shared__ int sh_eq[KPRE];
    int pair = blockIdx.x;
    topk_sorted<KPRE, 1024, 512>(g_keys + (size_t)pair * NA, NA,
                                 sh_key, sh_idx, sh_eq, hist);
    for (int k = threadIdx.x; k < KPRE; k += 512) {
        g_selidx[pair * KPRE + k] = sh_idx[k];
        g_selkey[pair * KPRE + k] = sh_key[k];
    }
}

// ---------------- stage 4: greedy NMS per (b,c) -----------------------------
__global__ void __launch_bounds__(256) nms_kernel() {
    int pair = blockIdx.x;
    int b = pair / NC;
    __shared__ float4 bx[KPRE];
    __shared__ float  area[KPRE];
    __shared__ int    keep[KPRE];
    int tid = threadIdx.x;

    for (int k = tid; k < KPRE; k += 256) {
        int idx = g_selidx[pair * KPRE + k];
        float4 v = g_boxes[b * NA + idx];
        bx[k] = v;
        area[k] = (v.z - v.x) * (v.w - v.y);
        keep[k] = (g_selkey[pair * KPRE + k] != 0u) ? 1 : 0;
    }
    __syncthreads();

    for (int i = 0; i < KPRE; i++) {
        if (keep[i]) {  // uniform read of shared -> no divergence across block
            float4 bi = bx[i];
            float ai = area[i];
            for (int j = i + 1 + tid; j < KPRE; j += 256) {
                if (keep[j]) {
                    float xx1 = fmaxf(bi.x, bx[j].x);
                    float yy1 = fmaxf(bi.y, bx[j].y);
                    float xx2 = fminf(bi.z, bx[j].z);
                    float yy2 = fminf(bi.w, bx[j].w);
                    float iw = fmaxf(xx2 - xx1, 0.0f);
                    float ih = fmaxf(yy2 - yy1, 0.0f);
                    float inter = iw * ih;
                    float u = ai + area[j] - inter;
                    if (inter / u > 0.5f) keep[j] = 0;   // NaN compares false, matches JAX
                }
            }
        }
        __syncthreads();
    }

    for (int k = tid; k < KPRE; k += 256)
        g_cand[pair * KPRE + k] = keep[k] ? g_selkey[pair * KPRE + k] : 0u;
}

// ---------------- stage 5: per-image top-100 + outputs ----------------------
__global__ void __launch_bounds__(512) final_kernel(const float* __restrict__ scale,
                                                    float* __restrict__ out) {
    __shared__ uint32_t hist[256];
    __shared__ uint32_t sh_key[128];
    __shared__ int sh_idx[128];
    __shared__ int sh_eq[MAXBOX];
    int b = blockIdx.x;
    topk_sorted<MAXBOX, 128, 512>(g_cand + (size_t)b * CAND_N, CAND_N,
                                  sh_key, sh_idx, sh_eq, hist);
    int tid = threadIdx.x;
    if (tid < MAXBOX) {
        uint32_t key = sh_key[tid];
        int f = sh_idx[tid];
        float prob = __uint_as_float(key);
        bool val = prob > 0.01f;
        int c = f / KPRE;
        int k = f - c * KPRE;
        int anchor = g_selidx[(b * NC + c) * KPRE + k];
        float4 bxv = g_boxes[b * NA + anchor];
        float s = scale[b];
        int o = (b * MAXBOX + tid) * 4;
        out[o + 0] = val ? bxv.x / s : 0.0f;
        out[o + 1] = val ? bxv.y / s : 0.0f;
        out[o + 2] = val ? bxv.z / s : 0.0f;
        out[o + 3] = val ? bxv.w / s : 0.0f;
        out[BB * MAXBOX * 4 + b * MAXBOX + tid]               = val ? (float)c : -1.0f;
        out[BB * MAXBOX * 4 + BB * MAXBOX + b * MAXBOX + tid] = val ? prob : 0.0f;
    }
}

// ---------------- launcher ---------------------------------------------------
extern "C" void kernel_launch(void* const* d_in, const int* in_sizes, int n_in,
                              void* d_out, int out_size) {
    // inputs (metadata order): image, anchors, regression, classification, scale
    const float4* anchors    = (const float4*)d_in[1];
    const float4* regression = (const float4*)d_in[2];
    const float*  cls        = (const float*)d_in[3];
    const float*  scale      = (const float*)d_in[4];

    decode_kernel<<<(BB * NA + 255) / 256, 256>>>(anchors, regression);

    dim3 tg((NA + 31) / 32, (NC + 31) / 32, BB);
    sigmoid_transpose_kernel<<<tg, dim3(32, 32)>>>(cls);

    select_kernel<<<NPAIR, 512>>>();
    nms_kernel<<<NPAIR, 256>>>();
    final_kernel<<<BB, 512>>>(scale, (float*)d_out);
}

// round 17
// speedup vs baseline: 1.0528x; 1.0030x over previous
#include <cuda_runtime.h>
#include <cstdint>

// Problem constants (fixed shapes for this problem)
#define BB     4
#define NA     49104
#define NC     80
#define KPRE   1000
#define MAXBOX 100
#define NPAIR  (BB*NC)
#define CAND_N (NC*KPRE)

// ---------------- scratch (static device globals; no allocations) ----------
__device__ uint32_t g_keys[(size_t)BB * NC * NA];   // ~63 MB: prob bits, transposed [B,C,N]
__device__ float4   g_boxes[BB * NA];               // decoded clipped boxes xyxy
__device__ int      g_selidx[NPAIR * KPRE];         // top-1000 anchor ids per (b,c), sorted
__device__ uint32_t g_selkey[NPAIR * KPRE];         // their prob bits (0 = invalid)
__device__ uint32_t g_cand[NPAIR * KPRE];           // post-NMS candidate keys

// ---------------- stage 1: box decode + clip -------------------------------
__global__ void decode_kernel(const float4* __restrict__ anchors,
                              const float4* __restrict__ reg) {
    int t = blockIdx.x * blockDim.x + threadIdx.x;
    if (t >= BB * NA) return;
    float4 a = anchors[t];   // (y1, x1, y2, x2)
    float4 r = reg[t];       // (dy, dx, dh, dw)
    float yca = (a.x + a.z) * 0.5f;
    float xca = (a.y + a.w) * 0.5f;
    float ha = a.z - a.x;
    float wa = a.w - a.y;
    float w = expf(r.w) * wa;
    float h = expf(r.z) * ha;
    float yc = r.x * ha + yca;
    float xc = r.y * wa + xca;
    float4 o;
    o.x = fmaxf(xc - w * 0.5f, 0.0f);
    o.y = fmaxf(yc - h * 0.5f, 0.0f);
    o.z = fminf(xc + w * 0.5f, 511.0f);
    o.w = fminf(yc + h * 0.5f, 511.0f);
    g_boxes[t] = o;
}

// ---------------- stage 2: sigmoid + threshold + transpose to [B,C,N] ------
__global__ void sigmoid_transpose_kernel(const float* __restrict__ cls) {
    __shared__ uint32_t tile[32][33];
    int b  = blockIdx.z;
    int n0 = blockIdx.x << 5;
    int c0 = blockIdx.y << 5;
    int c = c0 + threadIdx.x;
    int n = n0 + threadIdx.y;
    uint32_t v = 0u;
    if (n < NA && c < NC) {
        float x = cls[((size_t)b * NA + n) * NC + c];
        float p;
        if (x >= 0.0f) { p = 1.0f / (1.0f + expf(-x)); }
        else           { float e = expf(x); p = e / (1.0f + e); }
        v = (p > 0.01f) ? __float_as_uint(p) : 0u;   // positive float bits are order-preserving
    }
    tile[threadIdx.y][threadIdx.x] = v;
    __syncthreads();
    int cc = c0 + threadIdx.y;
    int nn = n0 + threadIdx.x;
    if (nn < NA && cc < NC)
        g_keys[((size_t)b * NC + cc) * NA + nn] = tile[threadIdx.x][threadIdx.y];
}

// ---------------- generic exact top-K sorted (key desc, idx asc) -----------
// Radix-select (4 x 8-bit passes) finds exact pivot + count of equals to take;
// collection + bitonic sort produce the K best in sorted order.
template <int K, int PADK, int T>
__device__ void topk_sorted(const uint32_t* __restrict__ keys, int n,
                            uint32_t* sh_key, int* sh_idx, int* sh_eq,
                            uint32_t* hist) {
    int tid = threadIdx.x;
    __shared__ uint32_t s_prefix;
    __shared__ int s_kth, s_chi, s_ceq;
    if (tid == 0) { s_prefix = 0u; s_kth = K; }

    for (int pass = 0; pass < 4; pass++) {
        int shift = 24 - 8 * pass;
        for (int d = tid; d < 256; d += T) hist[d] = 0u;
        __syncthreads();
        uint32_t prefix = s_prefix;
        uint32_t maskhi = pass ? (0xFFFFFFFFu << (shift + 8)) : 0u;
        for (int i = tid; i < n; i += T) {
            uint32_t kv = keys[i];
            if ((kv & maskhi) == prefix)
                atomicAdd(&hist[(kv >> shift) & 255u], 1u);
        }
        __syncthreads();
        if (tid == 0) {
            int kth = s_kth;
            int c = 0;
            for (int d = 255; d >= 0; d--) {
                c += (int)hist[d];
                if (c >= kth) {
                    s_prefix = prefix | ((uint32_t)d << shift);
                    s_kth = kth - (c - (int)hist[d]);
                    break;
                }
            }
        }
        __syncthreads();
    }

    uint32_t pivot = s_prefix;
    int rem = s_kth;   // how many ==pivot to take
    if (tid == 0) { s_chi = 0; s_ceq = 0; }
    __syncthreads();

    for (int i = tid; i < n; i += T) {
        uint32_t kv = keys[i];
        if (kv > pivot) {
            int p = atomicAdd(&s_chi, 1);
            sh_key[p] = kv; sh_idx[p] = i;
        } else if (kv == pivot) {
            int p = atomicAdd(&s_ceq, 1);
            if (p < rem) sh_eq[p] = i;
        }
    }
    __syncthreads();
    int chi = s_chi;   // == K - rem by construction
    for (int j = tid; j < rem; j += T) { sh_key[chi + j] = pivot; sh_idx[chi + j] = sh_eq[j]; }
    for (int j = K + tid; j < PADK; j += T) { sh_key[j] = 0u; sh_idx[j] = 0x7FFFFFFF; }
    __syncthreads();

    // bitonic sort: best-first (key desc, idx asc)
    for (int size = 2; size <= PADK; size <<= 1) {
        for (int stride = size >> 1; stride > 0; stride >>= 1) {
            for (int i = tid; i < PADK; i += T) {
                int j = i ^ stride;
                if (j > i) {
                    uint32_t ki = sh_key[i], kj = sh_key[j];
                    int ii = sh_idx[i], ij = sh_idx[j];
                    bool jBetter = (kj > ki) || (kj == ki && ij < ii);
                    bool dirDesc = ((i & size) == 0);
                    if (dirDesc == jBetter) {
                        sh_key[i] = kj; sh_key[j] = ki;
                        sh_idx[i] = ij; sh_idx[j] = ii;
                    }
                }
            }
            __syncthreads();
        }
    }
}

// ---------------- stage 3: per-(b,c) top-1000 sorted ------------------------
__global__ void __launch_bounds__(512) select_kernel() {
    __shared__ uint32_t hist[256];
    __shared__ uint32_t sh_key[1024];
    __shared__ int sh_idx[1024];
    __shared__ int sh_eq[KPRE];
    int pair = blockIdx.x;
    topk_sorted<KPRE, 1024, 512>(g_keys + (size_t)pair * NA, NA,
                                 sh_key, sh_idx, sh_eq, hist);
    for (int k = threadIdx.x; k < KPRE; k += 512) {
        g_selidx[pair * KPRE + k] = sh_idx[k];
        g_selkey[pair * KPRE + k] = sh_key[k];
    }
}

// ---------------- stage 4: greedy NMS per (b,c) -----------------------------
__global__ void __launch_bounds__(256) nms_kernel() {
    int pair = blockIdx.x;
    int b = pair / NC;
    __shared__ float4 bx[KPRE];
    __shared__ float  area[KPRE];
    __shared__ int    keep[KPRE];
    int tid = threadIdx.x;

    for (int k = tid; k < KPRE; k += 256) {
        int idx = g_selidx[pair * KPRE + k];
        float4 v = g_boxes[b * NA + idx];
        bx[k] = v;
        area[k] = (v.z - v.x) * (v.w - v.y);
        keep[k] = (g_selkey[pair * KPRE + k] != 0u) ? 1 : 0;
    }
    __syncthreads();

    for (int i = 0; i < KPRE; i++) {
        if (keep[i]) {  // uniform read of shared -> no divergence across block
            float4 bi = bx[i];
            float ai = area[i];
            for (int j = i + 1 + tid; j < KPRE; j += 256) {
                if (keep[j]) {
                    float xx1 = fmaxf(bi.x, bx[j].x);
                    float yy1 = fmaxf(bi.y, bx[j].y);
                    float xx2 = fminf(bi.z, bx[j].z);
                    float yy2 = fminf(bi.w, bx[j].w);
                    float iw = fmaxf(xx2 - xx1, 0.0f);
                    float ih = fmaxf(yy2 - yy1, 0.0f);
                    float inter = iw * ih;
                    float u = ai + area[j] - inter;
                    if (inter / u > 0.5f) keep[j] = 0;   // NaN compares false, matches JAX
                }
            }
        }
        __syncthreads();
    }

    for (int k = tid; k < KPRE; k += 256)
        g_cand[pair * KPRE + k] = keep[k] ? g_selkey[pair * KPRE + k] : 0u;
}

// ---------------- stage 5: per-image top-100 + outputs ----------------------
__global__ void __launch_bounds__(512) final_kernel(const float* __restrict__ scale,
                                                    float* __restrict__ out) {
    __shared__ uint32_t hist[256];
    __shared__ uint32_t sh_key[128];
    __shared__ int sh_idx[128];
    __shared__ int sh_eq[MAXBOX];
    int b = blockIdx.x;
    topk_sorted<MAXBOX, 128, 512>(g_cand + (size_t)b * CAND_N, CAND_N,
                                  sh_key, sh_idx, sh_eq, hist);
    int tid = threadIdx.x;
    if (tid < MAXBOX) {
        uint32_t key = sh_key[tid];
        int f = sh_idx[tid];
        float prob = __uint_as_float(key);
        bool val = prob > 0.01f;
        int c = f / KPRE;
        int k = f - c * KPRE;
        int anchor = g_selidx[(b * NC + c) * KPRE + k];
        float4 bxv = g_boxes[b * NA + anchor];
        float s = scale[b];
        int o = (b * MAXBOX + tid) * 4;
        out[o + 0] = val ? bxv.x / s : 0.0f;
        out[o + 1] = val ? bxv.y / s : 0.0f;
        out[o + 2] = val ? bxv.z / s : 0.0f;
        out[o + 3] = val ? bxv.w / s : 0.0f;
        out[BB * MAXBOX * 4 + b * MAXBOX + tid]               = val ? (float)c : -1.0f;
        out[BB * MAXBOX * 4 + BB * MAXBOX + b * MAXBOX + tid] = val ? prob : 0.0f;
    }
}

// ---------------- launcher ---------------------------------------------------
extern "C" void kernel_launch(void* const* d_in, const int* in_sizes, int n_in,
                              void* d_out, int out_size) {
    // inputs (metadata order): image, anchors, regression, classification, scale
    const float4* anchors    = (const float4*)d_in[1];
    const float4* regression = (const float4*)d_in[2];
    const float*  cls        = (const float*)d_in[3];
    const float*  scale      = (const float*)d_in[4];

    decode_kernel<<<(BB * NA + 255) / 256, 256>>>(anchors, regression);

    dim3 tg((NA + 31) / 32, (NC + 31) / 32, BB);
    sigmoid_transpose_kernel<<<tg, dim3(32, 32)>>>(cls);

    select_kernel<<<NPAIR, 512>>>();
    nms_kernel<<<NPAIR, 256>>>();
    final_kernel<<<BB, 512>>>(scale, (float*)d_out);
}